// round 7
// baseline (speedup 1.0000x reference)
#include <cuda_runtime.h>
#include <math.h>
#include <stdint.h>

#define NSNR 2048
#define NT   4096
#define NP   100
#define NI   99
#define TPB  256
#define NC   (NT / 4)      // 1024 chunks of 4 elements
#define CPT  (NC / TPB)    // 4 chunks per thread
#define NWARP (TPB / 32)
#define NACC 32

__device__ double       g_acc[NACC];   // zero-init; reset by last block each run
__device__ unsigned int g_ticket;      // self-resetting via atomicInc wrap

// Precomputed Thomas forward-elimination multipliers for tri(1,4,1), n=98.
struct CpTab { float v[98]; };
static constexpr CpTab make_cp() {
    CpTab t{};
    double c = 0.25;
    t.v[0] = (float)c;
    for (int i = 1; i < 98; i++) { c = 1.0 / (4.0 - c); t.v[i] = (float)c; }
    return t;
}
__constant__ CpTab d_cp = make_cp();

__device__ __forceinline__ void prefetch_l2(const void* p) {
    asm volatile("prefetch.global.L2 [%0];" :: "l"(p));
}

// Block-wide exclusive scan of one float per thread. Contains __syncthreads.
__device__ __forceinline__ float block_scan_excl(float v, float* warp_sums, float* total) {
    int lane = threadIdx.x & 31, wid = threadIdx.x >> 5;
    float x = v;
#pragma unroll
    for (int o = 1; o < 32; o <<= 1) {
        float y = __shfl_up_sync(0xffffffffu, x, o);
        if (lane >= o) x += y;
    }
    if (lane == 31) warp_sums[wid] = x;
    __syncthreads();
    if (wid == 0) {
        float w = (lane < NWARP) ? warp_sums[lane] : 0.0f;
#pragma unroll
        for (int o = 1; o < NWARP; o <<= 1) {
            float y = __shfl_up_sync(0xffffffffu, w, o);
            if (lane >= o) w += y;
        }
        if (lane < NWARP) warp_sums[lane] = w;
    }
    __syncthreads();
    float excl = (x - v) + (wid ? warp_sums[wid - 1] : 0.0f);
    *total = warp_sums[NWARP - 1];
    return excl;
}

// ---------------------------------------------------------------------------
// Striped load of |src| into fa[CPT][4] registers + two-level chunk scan.
// On exit: pfx[i] = exclusive prefix of increments at the start of chunk
// (tid + TPB*i); sLa[c] = last |x| of chunk c; *totalp = row total.
// Contains multiple __syncthreads.
// ---------------------------------------------------------------------------
__device__ __forceinline__ void chunk_scan(
    const float4* __restrict__ src4, float dt,
    float fa[CPT][4], float pfx[CPT],
    float* sCh, float* sLa, float* warp_sums, float* totalp)
{
    const int tid = threadIdx.x;
#pragma unroll
    for (int i = 0; i < CPT; i++) {
        float4 v = src4[tid + TPB * i];
        fa[i][0] = fabsf(v.x);
        fa[i][1] = fabsf(v.y);
        fa[i][2] = fabsf(v.z);
        fa[i][3] = fabsf(v.w);
        sLa[tid + TPB * i] = fa[i][3];
    }
    __syncthreads();

#pragma unroll
    for (int i = 0; i < CPT; i++) {
        int c = tid + TPB * i;
        float prev = (c == 0) ? 0.0f : sLa[c - 1];
        float e0 = (c == 0) ? 0.0f : 0.5f * dt * (fa[i][0] + prev);
        float e1 = 0.5f * dt * (fa[i][1] + fa[i][0]);
        float e2 = 0.5f * dt * (fa[i][2] + fa[i][1]);
        float e3 = 0.5f * dt * (fa[i][3] + fa[i][2]);
        sCh[c] = ((e0 + e1) + e2) + e3;
    }
    __syncthreads();

    // scan over 1024 chunk sums: thread t gathers chunks 4t..4t+3 (LDS.128)
    float4 g4 = reinterpret_cast<float4*>(sCh)[tid];
    float local = ((g4.x + g4.y) + g4.z) + g4.w;
    float total;
    float excl = block_scan_excl(local, warp_sums, &total);  // syncs order reads/writes
    float4 p4;
    p4.x = excl;
    p4.y = p4.x + g4.x;
    p4.z = p4.y + g4.y;
    p4.w = p4.z + g4.z;
    reinterpret_cast<float4*>(sCh)[tid] = p4;
    __syncthreads();

#pragma unroll
    for (int i = 0; i < CPT; i++) pfx[i] = sCh[tid + TPB * i];
    *totalp = total;
}

// ---------------------------------------------------------------------------
__global__ void __launch_bounds__(TPB, 7) wasserstein_kernel(
    const float* __restrict__ f, const float* __restrict__ obs,
    const float* __restrict__ t, float* __restrict__ out)
{
    __shared__ float  sCDF[NT];      // obs CDF for binary search (16 KB)
    __shared__ float  sCh[NC];       // chunk sums / prefixes (4 KB)
    __shared__ float  sLa[NC];       // last |x| per chunk (4 KB)
    __shared__ float4 scf4[NP];      // spline coeffs
    __shared__ float  sQ[NP];
    __shared__ float  sM[NP];
    __shared__ float  sdp[98];
    __shared__ float  warp_sums[NWARP];
    __shared__ float  red[NWARP];

    const int   row = blockIdx.x;
    const int   tid = threadIdx.x;
    const float dt  = t[1] - t[0];

    // warm L2 with the f row while phase A runs (no regs, no smem)
    {
        const float4* gf = reinterpret_cast<const float4*>(f + (size_t)row * NT);
#pragma unroll
        for (int i = 0; i < CPT; i++) prefetch_l2(gf + tid + TPB * i);
    }

    float fa[CPT][4], pfx[CPT];
    float total;

    // ================= Phase A: obs -> spline coefficients =================
    chunk_scan(reinterpret_cast<const float4*>(obs + (size_t)row * NT), dt,
               fa, pfx, sCh, sLa, warp_sums, &total);

    // write element-level CDF (STS.128 per chunk)
#pragma unroll
    for (int i = 0; i < CPT; i++) {
        int c = tid + TPB * i;
        float prev = (c == 0) ? 0.0f : sLa[c - 1];
        float S = pfx[i];
        float4 o;
        S += (c == 0) ? 0.0f : 0.5f * dt * (fa[i][0] + prev);  o.x = S;
        S += 0.5f * dt * (fa[i][1] + fa[i][0]);                o.y = S;
        S += 0.5f * dt * (fa[i][2] + fa[i][1]);                o.z = S;
        S += 0.5f * dt * (fa[i][3] + fa[i][2]);                o.w = S;
        reinterpret_cast<float4*>(sCDF)[c] = o;
    }
    __syncthreads();

    // inverse CDF at 100 quantiles (binary search)
    if (tid < NP) {
        float p = (float)tid / 99.0f;
        float target = p * total;
        int lo = 0, hi = NT - 1;
        while (lo < hi) {
            int mid = (lo + hi + 1) >> 1;
            if (sCDF[mid] <= target) lo = mid; else hi = mid - 1;
        }
        int j = min(lo, NT - 2);
        float den = sCDF[j + 1] - sCDF[j];
        float q = (float)j * dt;
        if (den > 0.0f) q += (target - sCDF[j]) * dt / den;
        sQ[tid] = q;
    }
    __syncthreads();

    // u_i = rhs_i * cp_i in parallel (98 threads)
    if (tid < 98) {
        const float S6 = 6.0f * 9801.0f;   // 6 / h^2
        float rhs = S6 * (sQ[tid + 2] - 2.0f * sQ[tid + 1] + sQ[tid]);
        sdp[tid] = rhs * d_cp.v[tid];
    }
    __syncthreads();

    // serial Thomas recurrences (single FFMA chains)
    if (tid == 0) {
        float dp = sdp[0];
        for (int i = 1; i < 98; i++) {
            dp = fmaf(-d_cp.v[i], dp, sdp[i]);
            sdp[i] = dp;
        }
        sM[0] = 0.0f;
        sM[NP - 1] = 0.0f;
        float mnext = sdp[97];
        sM[98] = mnext;
        for (int i = 96; i >= 0; i--) {
            mnext = fmaf(-d_cp.v[i], mnext, sdp[i]);
            sM[i + 1] = mnext;
        }
    }
    __syncthreads();

    if (tid < NI) {
        const float H    = (float)(1.0 / 99.0);
        const float invH = 99.0f;
        float Mi = sM[tid], Mi1 = sM[tid + 1];
        float4 c;
        c.x = sQ[tid];
        c.y = (sQ[tid + 1] - sQ[tid]) * invH - H * (2.0f * Mi + Mi1) * (1.0f / 6.0f);
        c.z = Mi * 0.5f;
        c.w = (Mi1 - Mi) * (invH / 6.0f);
        scf4[tid] = c;
    }
    __syncthreads();

    // ================= Phase B: f -> loss contribution =================
    chunk_scan(reinterpret_cast<const float4*>(f + (size_t)row * NT), dt,
               fa, pfx, sCh, sLa, warp_sums, &total);

    const float invT = 1.0f / total;
    float gsum = 0.0f;
    float gFirst = 0.0f, gLast = 0.0f;
    {
        int   idx = -1;
        float4 cf = make_float4(0.f, 0.f, 0.f, 0.f);
#pragma unroll
        for (int i = 0; i < CPT; i++) {
            int c = tid + TPB * i;
            float prev = (c == 0) ? 0.0f : sLa[c - 1];
            float S = pfx[i];
#pragma unroll
            for (int k = 0; k < 4; k++) {
                int j = 4 * c + k;
                float left = (k == 0) ? prev : fa[i][k - 1];
                float e = (j == 0) ? 0.0f : 0.5f * dt * (fa[i][k] + left);
                S += e;

                float xi = fminf(S * invT, 1.0f);
                int ki = min((int)(xi * 99.0f), NI - 1);
                if (ki != idx) { idx = ki; cf = scf4[ki]; }   // rare: F monotone
                float dx = xi - (float)idx * (float)(1.0 / 99.0);
                float val = cf.x + dx * (cf.y + dx * (cf.z + dx * cf.w));
                float diff = (float)j * dt - val;
                float g = diff * diff * (fa[i][k] * invT);
                gsum += g;
                if (i == 0 && k == 0) gFirst = g;   // j==0 lives in (tid==0,i=0,k=0)
                if (i == CPT - 1 && k == 3) gLast = g; // j==NT-1 in (tid==255,i=3,k=3)
            }
        }
    }
    if (tid == 0)       gsum -= 0.5f * gFirst;   // trapezoid edge j=0
    if (tid == TPB - 1) gsum -= 0.5f * gLast;    // trapezoid edge j=NT-1

#pragma unroll
    for (int o = 16; o; o >>= 1) gsum += __shfl_down_sync(0xffffffffu, gsum, o);
    if ((tid & 31) == 0) red[tid >> 5] = gsum;
    __syncthreads();

    if (tid == 0) {
        float s = 0.0f;
#pragma unroll
        for (int w = 0; w < NWARP; w++) s += red[w];
        double my = (double)(dt * s);
        atomicAdd(&g_acc[row & (NACC - 1)], my);
        __threadfence();
        unsigned tk = atomicInc(&g_ticket, NSNR - 1);   // wraps to 0 automatically
        if (tk == NSNR - 1) {
            double tot = 0.0;
#pragma unroll
            for (int w = 0; w < NACC; w++) { tot += g_acc[w]; g_acc[w] = 0.0; }
            out[0] = (float)tot;
        }
    }
}

// ---------------------------------------------------------------------------
extern "C" void kernel_launch(void* const* d_in, const int* in_sizes, int n_in,
                              void* d_out, int out_size)
{
    const float* f   = (const float*)d_in[0];
    const float* obs = (const float*)d_in[1];
    const float* t   = (const float*)d_in[2];

    wasserstein_kernel<<<NSNR, TPB>>>(f, obs, t, (float*)d_out);
}

// round 8
// speedup vs baseline: 1.2231x; 1.2231x over previous
#include <cuda_runtime.h>
#include <math.h>
#include <stdint.h>

#define NSNR 2048
#define NT   4096
#define NP   100
#define NI   99
#define TPB  256
#define NC   (NT / 4)      // 1024 chunks of 4 elements
#define CPT  (NC / TPB)    // 4 chunks per thread
#define NWARP (TPB / 32)
#define NACC 32

__device__ double       g_acc[NACC];   // zero-init; reset by last block each run
__device__ unsigned int g_ticket;      // self-resetting via atomicInc wrap

// Precomputed Thomas forward-elimination multipliers for tri(1,4,1), n=98.
struct CpTab { float v[98]; };
static constexpr CpTab make_cp() {
    CpTab t{};
    double c = 0.25;
    t.v[0] = (float)c;
    for (int i = 1; i < 98; i++) { c = 1.0 / (4.0 - c); t.v[i] = (float)c; }
    return t;
}
__constant__ CpTab d_cp = make_cp();

// Block-wide exclusive scan of one float per thread. Contains __syncthreads.
__device__ __forceinline__ float block_scan_excl(float v, float* warp_sums, float* total) {
    int lane = threadIdx.x & 31, wid = threadIdx.x >> 5;
    float x = v;
#pragma unroll
    for (int o = 1; o < 32; o <<= 1) {
        float y = __shfl_up_sync(0xffffffffu, x, o);
        if (lane >= o) x += y;
    }
    if (lane == 31) warp_sums[wid] = x;
    __syncthreads();
    if (wid == 0) {
        float w = (lane < NWARP) ? warp_sums[lane] : 0.0f;
#pragma unroll
        for (int o = 1; o < NWARP; o <<= 1) {
            float y = __shfl_up_sync(0xffffffffu, w, o);
            if (lane >= o) w += y;
        }
        if (lane < NWARP) warp_sums[lane] = w;
    }
    __syncthreads();
    float excl = (x - v) + (wid ? warp_sums[wid - 1] : 0.0f);
    *total = warp_sums[NWARP - 1];
    return excl;
}

// ---------------------------------------------------------------------------
// Striped load of |src| + two-level PLAIN prefix scan of |y| chunk sums.
// On exit: fa holds |y|; pfx[i] = exclusive prefix of |y| at chunk start;
// *Ptot = sum of |y| over the row. No neighbor exchange needed (closed-form
// trapezoid: S_j = dt*P_j - hd*(y0 + y_j)). Contains __syncthreads.
// ---------------------------------------------------------------------------
__device__ __forceinline__ void chunk_scan(
    const float4* __restrict__ src4,
    float fa[CPT][4], float pfx[CPT],
    float* sCh, float* warp_sums, float* Ptot)
{
    const int tid = threadIdx.x;
#pragma unroll
    for (int i = 0; i < CPT; i++) {
        float4 v = src4[tid + TPB * i];
        fa[i][0] = fabsf(v.x);
        fa[i][1] = fabsf(v.y);
        fa[i][2] = fabsf(v.z);
        fa[i][3] = fabsf(v.w);
        sCh[tid + TPB * i] = ((fa[i][0] + fa[i][1]) + fa[i][2]) + fa[i][3];
    }
    __syncthreads();

    // scan over 1024 chunk sums: thread t gathers chunks 4t..4t+3 (LDS.128)
    float4 g4 = reinterpret_cast<float4*>(sCh)[tid];
    float local = ((g4.x + g4.y) + g4.z) + g4.w;
    float total;
    float excl = block_scan_excl(local, warp_sums, &total);  // syncs order reads/writes
    float4 p4;
    p4.x = excl;
    p4.y = p4.x + g4.x;
    p4.z = p4.y + g4.y;
    p4.w = p4.z + g4.z;
    reinterpret_cast<float4*>(sCh)[tid] = p4;
    __syncthreads();

#pragma unroll
    for (int i = 0; i < CPT; i++) pfx[i] = sCh[tid + TPB * i];
    *Ptot = total;
}

// ---------------------------------------------------------------------------
__global__ void __launch_bounds__(TPB, 8) wasserstein_kernel(
    const float* __restrict__ f, const float* __restrict__ obs,
    const float* __restrict__ t, float* __restrict__ out)
{
    __shared__ float  sCDF[NT];      // obs CDF for binary search (16 KB)
    __shared__ float  sCh[NC];       // chunk sums / prefixes (4 KB)
    __shared__ float4 scf4[NP];      // spline coeffs
    __shared__ float  sQ[NP];
    __shared__ float  sM[NP];
    __shared__ float  sdp[98];
    __shared__ float  warp_sums[NWARP];
    __shared__ float  red[NWARP];
    __shared__ float  sEnds[2];      // y0, ylast of current row

    const int   row = blockIdx.x;
    const int   tid = threadIdx.x;
    const float dt  = t[1] - t[0];
    const float hd  = 0.5f * dt;

    float fa[CPT][4], pfx[CPT];
    float Ptot;

    // ================= Phase A: obs -> spline coefficients =================
    chunk_scan(reinterpret_cast<const float4*>(obs + (size_t)row * NT),
               fa, pfx, sCh, warp_sums, &Ptot);

    if (tid == 0)       sEnds[0] = fa[0][0];           // y[0]
    if (tid == TPB - 1) sEnds[1] = fa[CPT - 1][3];     // y[NT-1]
    __syncthreads();

    const float y0A = sEnds[0];
    const float totalA = dt * Ptot - hd * (y0A + sEnds[1]);

    // element CDF via closed form: S_k = base + hd*(r_k + r_{k-1}),
    // base = dt*pfx - hd*y0, r = running sum of |y| within chunk.
#pragma unroll
    for (int i = 0; i < CPT; i++) {
        int c = tid + TPB * i;
        float base = dt * pfx[i] - hd * y0A;
        float4 o;
        float rprev = 0.0f, r = fa[i][0];
        o.x = fmaf(hd, r + rprev, base); rprev = r; r += fa[i][1];
        o.y = fmaf(hd, r + rprev, base); rprev = r; r += fa[i][2];
        o.z = fmaf(hd, r + rprev, base); rprev = r; r += fa[i][3];
        o.w = fmaf(hd, r + rprev, base);
        reinterpret_cast<float4*>(sCDF)[c] = o;
    }
    __syncthreads();

    // inverse CDF at 100 quantiles (binary search)
    if (tid < NP) {
        float p = (float)tid / 99.0f;
        float target = p * totalA;
        int lo = 0, hi = NT - 1;
        while (lo < hi) {
            int mid = (lo + hi + 1) >> 1;
            if (sCDF[mid] <= target) lo = mid; else hi = mid - 1;
        }
        int j = min(lo, NT - 2);
        float den = sCDF[j + 1] - sCDF[j];
        float q = (float)j * dt;
        if (den > 0.0f) q += (target - sCDF[j]) * dt / den;
        sQ[tid] = q;
    }
    __syncthreads();

    // u_i = rhs_i * cp_i in parallel (98 threads)
    if (tid < 98) {
        const float S6 = 6.0f * 9801.0f;   // 6 / h^2
        float rhs = S6 * (sQ[tid + 2] - 2.0f * sQ[tid + 1] + sQ[tid]);
        sdp[tid] = rhs * d_cp.v[tid];
    }
    __syncthreads();

    // serial Thomas recurrences (single FFMA chains)
    if (tid == 0) {
        float dp = sdp[0];
        for (int i = 1; i < 98; i++) {
            dp = fmaf(-d_cp.v[i], dp, sdp[i]);
            sdp[i] = dp;
        }
        sM[0] = 0.0f;
        sM[NP - 1] = 0.0f;
        float mnext = sdp[97];
        sM[98] = mnext;
        for (int i = 96; i >= 0; i--) {
            mnext = fmaf(-d_cp.v[i], mnext, sdp[i]);
            sM[i + 1] = mnext;
        }
    }
    __syncthreads();

    if (tid < NI) {
        const float H    = (float)(1.0 / 99.0);
        const float invH = 99.0f;
        float Mi = sM[tid], Mi1 = sM[tid + 1];
        float4 c;
        c.x = sQ[tid];
        c.y = (sQ[tid + 1] - sQ[tid]) * invH - H * (2.0f * Mi + Mi1) * (1.0f / 6.0f);
        c.z = Mi * 0.5f;
        c.w = (Mi1 - Mi) * (invH / 6.0f);
        scf4[tid] = c;
    }
    __syncthreads();

    // ================= Phase B: f -> loss contribution =================
    chunk_scan(reinterpret_cast<const float4*>(f + (size_t)row * NT),
               fa, pfx, sCh, warp_sums, &Ptot);

    if (tid == 0)       sEnds[0] = fa[0][0];
    if (tid == TPB - 1) sEnds[1] = fa[CPT - 1][3];
    __syncthreads();

    const float y0B = sEnds[0];
    const float total = dt * Ptot - hd * (y0B + sEnds[1]);
    const float invT = 1.0f / total;

    float gsum = 0.0f;
    float gFirst = 0.0f, gLast = 0.0f;
#pragma unroll
    for (int i = 0; i < CPT; i++) {
        int c = tid + TPB * i;
        float base = dt * pfx[i] - hd * y0B;
        float rprev = 0.0f, r = 0.0f;
#pragma unroll
        for (int k = 0; k < 4; k++) {
            int j = 4 * c + k;
            r += fa[i][k];
            float S = fmaf(hd, r + rprev, base);
            rprev = r;

            float xi = fminf(fmaxf(S * invT, 0.0f), 1.0f);
            int idx = min((int)(xi * 99.0f), NI - 1);
            float dx = xi - (float)idx * (float)(1.0 / 99.0);
            float4 cf = scf4[idx];
            float val = cf.x + dx * (cf.y + dx * (cf.z + dx * cf.w));
            float diff = (float)j * dt - val;
            float g = diff * diff * (fa[i][k] * invT);
            gsum += g;
            if (i == 0 && k == 0) gFirst = g;        // j==0 only for tid==0
            if (i == CPT - 1 && k == 3) gLast = g;   // j==NT-1 only for tid==255
        }
    }
    if (tid == 0)       gsum -= 0.5f * gFirst;   // trapezoid edge j=0
    if (tid == TPB - 1) gsum -= 0.5f * gLast;    // trapezoid edge j=NT-1

#pragma unroll
    for (int o = 16; o; o >>= 1) gsum += __shfl_down_sync(0xffffffffu, gsum, o);
    if ((tid & 31) == 0) red[tid >> 5] = gsum;
    __syncthreads();

    if (tid == 0) {
        float s = 0.0f;
#pragma unroll
        for (int w = 0; w < NWARP; w++) s += red[w];
        double my = (double)(dt * s);
        atomicAdd(&g_acc[row & (NACC - 1)], my);
        __threadfence();
        unsigned tk = atomicInc(&g_ticket, NSNR - 1);   // wraps to 0 automatically
        if (tk == NSNR - 1) {
            double tot = 0.0;
#pragma unroll
            for (int w = 0; w < NACC; w++) { tot += g_acc[w]; g_acc[w] = 0.0; }
            out[0] = (float)tot;
        }
    }
}

// ---------------------------------------------------------------------------
extern "C" void kernel_launch(void* const* d_in, const int* in_sizes, int n_in,
                              void* d_out, int out_size)
{
    const float* f   = (const float*)d_in[0];
    const float* obs = (const float*)d_in[1];
    const float* t   = (const float*)d_in[2];

    wasserstein_kernel<<<NSNR, TPB>>>(f, obs, t, (float*)d_out);
}